// round 6
// baseline (speedup 1.0000x reference)
#include <cuda_runtime.h>
#include <cstdint>

// FlowNet correlation on GB300/B200 — R5: latency-ordered pipeline.
// out[b, dyi*21+dxi, h, w] = (1/256) * sum_c in1[b,c,h,w] * in2[b,c,h+dy,w+dx]
// dy = 2*(dyi-10), dx = 2*(dxi-10), zero padding.
// Shapes: B=8, C=256, H=96, W=128, G=21, D=441.
//
//  - Parity-packed smem rows -> contiguous 24-float key windows, LDS.128.
//  - CTA(32,11): one (b,h), 11 dy rows, all 128 w. Thread: 4 w x 21 dx.
//  - FFMA2 (fma.rn.f32x2) with operands straight from LDS.128 pairs.
//  - R5: single barrier/chunk with order LDG -> compute -> STS -> bar
//    (R4 stalled on the LDG scoreboard at STS before compute started);
//    LDG via persistent pointers + constant stride (kills alu=19% addressing).

#define CB    8
#define CC_   256
#define HH    96
#define WW    128
#define GG    21
#define DD    441
#define CHK   8
#define NCHK  32
#define NROW  11
#define SW    84
#define NTHR  352

#define B_BUF_FLOATS 14784
#define A_BUF_FLOATS 1024
#define A_REGION_OFF (2 * B_BUF_FLOATS)
#define SMEM_FLOATS  (2 * B_BUF_FLOATS + 2 * A_BUF_FLOATS)
#define SMEM_BYTES   (SMEM_FLOATS * 4)           // 126464

// float4 stride between channel chunks
#define CADV4 ((CHK * HH * WW) / 4)              // 24576

__device__ __forceinline__ uint64_t pk2(float lo, float hi) {
    uint64_t r;
    asm("mov.b64 %0, {%1, %2};" : "=l"(r) : "f"(lo), "f"(hi));
    return r;
}
__device__ __forceinline__ void upk2(uint64_t v, float& lo, float& hi) {
    asm("mov.b64 {%0, %1}, %2;" : "=f"(lo), "=f"(hi) : "l"(v));
}
__device__ __forceinline__ void ffma2(uint64_t& c, uint64_t a, uint64_t b) {
    asm("fma.rn.f32x2 %0, %1, %2, %0;" : "+l"(c) : "l"(a), "l"(b));
}

__global__ __launch_bounds__(NTHR, 1)
void corr_kernel(const float* __restrict__ in1,
                 const float* __restrict__ in2,
                 float* __restrict__ out)
{
    extern __shared__ float sm[];

    const int tx = threadIdx.x;
    const int ty = threadIdx.y;
    const int tid = ty * 32 + tx;
    const int s  = blockIdx.x;                  // dy half
    const int h  = blockIdx.y;
    const int b  = blockIdx.z;

    // ---- zero parity-halo regions of both buffers ----
    for (int i = tid; i < 2 * CHK * NROW * 2 * 20; i += NTHR) {
        int hseg = i % 20;
        int rest = i / 20;
        int par  = rest & 1;  rest >>= 1;
        int row  = rest % NROW; rest /= NROW;
        int ci   = rest % CHK;
        int buf  = rest / CHK;
        int idx  = (hseg < 10) ? hseg : (64 + hseg);
        sm[buf * B_BUF_FLOATS + ((ci * NROW + row) * 2 + par) * SW + idx] = 0.0f;
    }
    __syncthreads();

    const int par    = tx >> 4;
    const int xi     = tx & 15;
    const int dy_idx = s * NROW + ty;
    const bool active = (dy_idx < GG);
    const int base_w = 8 * xi + par;

    // paired accumulators: accp[kk][p] covers dxi (2p,2p+1) for even kk,
    // (1+2p,2+2p) for odd kk. Scalar leftover: dxi=20 (kk even), dxi=0 (kk odd).
    uint64_t accp[4][10];
    float    accs[4];
#pragma unroll
    for (int kk = 0; kk < 4; ++kk) {
        accs[kk] = 0.0f;
#pragma unroll
        for (int p = 0; p < 10; ++p) accp[kk][p] = 0ull;
    }

    // ---- persistent global pointers (chunk-invariant task decomposition) ----
    // B tasks: t = tid + 352*i, i=0..7 ; m=t&31, ci=(t>>5)&7, j=t>>8 (row 0..10)
    // A task : tid<256 ; m=tid&31, ci=tid>>5
    const float4* pB[8];
    bool vB[8];
#pragma unroll
    for (int i = 0; i < 8; ++i) {
        const int t  = tid + NTHR * i;
        const int m  = t & 31;
        const int ci = (t >> 5) & 7;
        const int j  = t >> 8;
        const int r  = h + 2 * (s * NROW + j) - 20;
        vB[i] = ((unsigned)r < (unsigned)HH);
        const int rr = vB[i] ? r : 0;
        pB[i] = reinterpret_cast<const float4*>(
            in2 + ((((long)b * CC_ + ci) * HH + rr) * WW + 4 * m));
    }
    const float4* pA = reinterpret_cast<const float4*>(
        in1 + ((((long)b * CC_ + (tid >> 5)) * HH + h) * WW + 4 * (tid & 31)));

    float4 rB[8];
    float4 rA = make_float4(0.f, 0.f, 0.f, 0.f);

    auto loadRegs = [&]() {
#pragma unroll
        for (int i = 0; i < 8; ++i) {
            rB[i] = vB[i] ? pB[i][0] : make_float4(0.f, 0.f, 0.f, 0.f);
            pB[i] += CADV4;
        }
        if (tid < 256) {
            rA = pA[0];
        }
        pA += CADV4;
    };

    auto stsRegs = [&](int buf) {
        float* B = sm + buf * B_BUF_FLOATS;
#pragma unroll
        for (int i = 0; i < 8; ++i) {
            const int t  = tid + NTHR * i;
            const int m  = t & 31;
            const int ci = (t >> 5) & 7;
            const int j  = t >> 8;
            float* pe = B + ((ci * NROW + j) * 2 + 0) * SW + 2 * m + 10;
            float* po = B + ((ci * NROW + j) * 2 + 1) * SW + 2 * m + 10;
            *reinterpret_cast<float2*>(pe) = make_float2(rB[i].x, rB[i].z);
            *reinterpret_cast<float2*>(po) = make_float2(rB[i].y, rB[i].w);
        }
        if (tid < 256) {
            const int m  = tid & 31;
            const int ci = tid >> 5;
            float* A = sm + A_REGION_OFF + buf * A_BUF_FLOATS;
            float* pe = A + (ci * 2 + 0) * 64 + 2 * m;
            float* po = A + (ci * 2 + 1) * 64 + 2 * m;
            *reinterpret_cast<float2*>(pe) = make_float2(rA.x, rA.z);
            *reinterpret_cast<float2*>(po) = make_float2(rA.y, rA.w);
        }
    };

    auto computeBuf = [&](int buf) {
        const float* Bb = sm + buf * B_BUF_FLOATS;
        const float* Ab = sm + A_REGION_OFF + buf * A_BUF_FLOATS;
#pragma unroll
        for (int ci = 0; ci < CHK; ++ci) {
            const float4 q4 = *reinterpret_cast<const float4*>(
                Ab + (ci * 2 + par) * 64 + 4 * xi);
            uint64_t qp[4];
            qp[0] = pk2(q4.x, q4.x);
            qp[1] = pk2(q4.y, q4.y);
            qp[2] = pk2(q4.z, q4.z);
            qp[3] = pk2(q4.w, q4.w);

            // 24-float window as 6 LDS.128, each yielding two 64-bit
            // even-aligned pairs directly (no repack movs).
            const ulonglong2* Bq = reinterpret_cast<const ulonglong2*>(
                Bb + ((ci * NROW + ty) * 2 + par) * SW + 4 * xi);
            uint64_t ep[12];
#pragma unroll
            for (int t = 0; t < 6; ++t) {
                const ulonglong2 v = Bq[t];
                ep[2 * t]     = v.x;
                ep[2 * t + 1] = v.y;
            }

#pragma unroll
            for (int p = 0; p < 10; ++p) {
                ffma2(accp[0][p], qp[0], ep[p]);
                ffma2(accp[1][p], qp[1], ep[p + 1]);
                ffma2(accp[2][p], qp[2], ep[p + 1]);
                ffma2(accp[3][p], qp[3], ep[p + 2]);
            }
            // scalar leftovers: kk even -> dxi=20; kk odd -> dxi=0
            float lo10, hi10, lo11, hi11, lo0, hi0, lo1, hi1;
            upk2(ep[10], lo10, hi10);
            upk2(ep[11], lo11, hi11);
            upk2(ep[0],  lo0,  hi0);
            upk2(ep[1],  lo1,  hi1);
            accs[0] = fmaf(q4.x, lo10, accs[0]);
            accs[2] = fmaf(q4.z, lo11, accs[2]);
            accs[1] = fmaf(q4.y, hi0,  accs[1]);
            accs[3] = fmaf(q4.w, hi1,  accs[3]);
        }
    };

    // ---- software pipeline, one barrier per chunk, LDG->compute->STS->bar ----
    loadRegs();                 // chunk 0
    stsRegs(0);
    __syncthreads();

    for (int k = 0; k < NCHK; ++k) {
        const int cur = k & 1;
        if (k + 1 < NCHK) loadRegs();          // LDG chunk k+1 (latency hidden
        if (active) computeBuf(cur);           //  under this compute block)
        if (k + 1 < NCHK) stsRegs(1 - cur);    // buffer drained at bar k-1
        __syncthreads();                       // cur read + other written
    }

    // ---- write results ----
    if (active) {
        const float scale = 1.0f / 256.0f;
        const int obase = ((b * DD + dy_idx * GG) * HH + h) * WW + base_w;
#pragma unroll
        for (int kk = 0; kk < 4; ++kk) {
            const int dxi0 = (kk & 1) ? 1 : 0;
#pragma unroll
            for (int p = 0; p < 10; ++p) {
                float lo, hi;
                upk2(accp[kk][p], lo, hi);
                const int d0 = dxi0 + 2 * p;
                out[obase + d0 * (HH * WW) + 2 * kk]       = lo * scale;
                out[obase + (d0 + 1) * (HH * WW) + 2 * kk] = hi * scale;
            }
            const int ds = (kk & 1) ? 0 : 20;
            out[obase + ds * (HH * WW) + 2 * kk] = accs[kk] * scale;
        }
    }
}

extern "C" void kernel_launch(void* const* d_in, const int* in_sizes, int n_in,
                              void* d_out, int out_size)
{
    const float* in1 = (const float*)d_in[0];
    const float* in2 = (const float*)d_in[1];
    float* out = (float*)d_out;

    (void)in_sizes; (void)n_in; (void)out_size;

    cudaFuncSetAttribute(corr_kernel,
                         cudaFuncAttributeMaxDynamicSharedMemorySize,
                         SMEM_BYTES);

    dim3 grid(2, HH, CB);
    dim3 block(32, NROW, 1);
    corr_kernel<<<grid, block, SMEM_BYTES>>>(in1, in2, out);
}

// round 8
// speedup vs baseline: 1.1076x; 1.1076x over previous
#include <cuda_runtime.h>
#include <cstdint>

// FlowNet correlation on GB300/B200 — R7 (= R6 design, infra retry):
// cp.async 3-stage pipeline from pre-packed gmem scratch.
//
// out[b, dyi*21+dxi, h, w] = (1/256) * sum_c in1[b,c,h,w] * in2[b,c,h+dy,w+dx]
// dy = 2*(dyi-10), dx = 2*(dxi-10), zero padding.
// Shapes: B=8, C=256, H=96, W=128, G=21, D=441.
//
// Prepass: parity-pack in2 rows into g_pack2[b][c][r][2][84] (10-float zero
// halos each side) and in1 rows into g_pack1[b][c][h][2][64].
// Main: CTA(32,11) per (b,h,dy-half); 3-stage smem ring filled by 16B
// cp.async.cg; compute = FFMA2 with operands straight from LDS.128 pairs.
// Removes: STS->BAR drain cost, LDG scoreboard stall before compute,
// per-chunk 64-bit addressing ALU (R2-R5's three measured bottlenecks).

#define CB    8
#define CC_   256
#define HH    96
#define WW    128
#define GG    21
#define DD    441
#define CHK   8
#define NCHK  32
#define NROW  11
#define NTHR  352

// stage layout (floats): B [8][11][168] = 14784, then A [8][128] = 1024
#define B_STAGE_FLOATS 14784
#define STAGE_FLOATS   15808
#define STAGE_BYTES    63232            // 15808*4
#define NSTAGE         3
#define SMEM_BYTES     (NSTAGE * STAGE_BYTES)   // 189696

#define NB_TASKS  3696                  // 8*11*42 quads
#define NTASKS    3952                  // + 8*32 A quads
#define TPT       12                    // tasks per thread (ceil 3952/352)

// packed scratch (static device arrays — allowed scratch mechanism)
__device__ float g_pack2[(long)CB * CC_ * HH * 168];   // 132 MB
__device__ float g_pack1[(long)CB * CC_ * HH * 128];   // 100 MB

__device__ __forceinline__ uint32_t smem_u32(const void* p) {
    uint32_t a;
    asm("{ .reg .u64 t; cvta.to.shared.u64 t, %1; cvt.u32.u64 %0, t; }"
        : "=r"(a) : "l"(p));
    return a;
}
__device__ __forceinline__ uint64_t pk2(float lo, float hi) {
    uint64_t r;
    asm("mov.b64 %0, {%1, %2};" : "=l"(r) : "f"(lo), "f"(hi));
    return r;
}
__device__ __forceinline__ void upk2(uint64_t v, float& lo, float& hi) {
    asm("mov.b64 {%0, %1}, %2;" : "=f"(lo), "=f"(hi) : "l"(v));
}
__device__ __forceinline__ void ffma2(uint64_t& c, uint64_t a, uint64_t b) {
    asm("fma.rn.f32x2 %0, %1, %2, %0;" : "+l"(c) : "l"(a), "l"(b));
}
__device__ __forceinline__ void cp16(uint32_t dst, const float* src) {
    asm volatile("cp.async.cg.shared.global [%0], [%1], 16;"
                 :: "r"(dst), "l"(src));
}
__device__ __forceinline__ void cp_commit() {
    asm volatile("cp.async.commit_group;" ::: "memory");
}

// ---------------- prepass: parity-pack both inputs ----------------
__global__ void pack_kernel(const float* __restrict__ in1,
                            const float* __restrict__ in2)
{
    const long row = blockIdx.x;          // (b*256+c)*96 + r, 196608 rows
    const int  t   = threadIdx.x;
    if (blockIdx.y == 0) {
        // in2 -> g_pack2 row [2][84], halos zero
        float* dst = g_pack2 + row * 168;
        if (t < 32) {
            const float4 v = reinterpret_cast<const float4*>(in2 + row * 128)[t];
            *reinterpret_cast<float2*>(dst + 10 + 2 * t) = make_float2(v.x, v.z);
            *reinterpret_cast<float2*>(dst + 94 + 2 * t) = make_float2(v.y, v.w);
        } else if (t < 72) {
            const int h40 = t - 32;            // 40 halo floats
            const int par = h40 / 20;
            const int off = h40 % 20;
            const int pos = (off < 10) ? off : (64 + off);
            dst[par * 84 + pos] = 0.0f;
        }
    } else {
        // in1 -> g_pack1 row [2][64]
        if (t < 32) {
            const float4 v = reinterpret_cast<const float4*>(in1 + row * 128)[t];
            float* dst = g_pack1 + row * 128;
            *reinterpret_cast<float2*>(dst + 2 * t)      = make_float2(v.x, v.z);
            *reinterpret_cast<float2*>(dst + 64 + 2 * t) = make_float2(v.y, v.w);
        }
    }
}

// ---------------- main kernel ----------------
__global__ __launch_bounds__(NTHR, 1)
void corr_kernel(float* __restrict__ out)
{
    extern __shared__ float sm[];
    const uint32_t smbase = smem_u32(sm);

    const int tx  = threadIdx.x;
    const int ty  = threadIdx.y;               // dy row within CTA
    const int tid = ty * 32 + tx;
    const int s   = blockIdx.x;                // dy half
    const int h   = blockIdx.y;
    const int b   = blockIdx.z;

    const int par    = tx >> 4;
    const int xi     = tx & 15;
    const int dy_idx = s * NROW + ty;
    const bool active = (dy_idx < GG);
    const int base_w = 8 * xi + par;

    // ---- per-thread cp.async task table (computed once) ----
    // task i: idx = tid + 352*i.
    //   idx <  3696 : B quad. ci=idx/462, j=(idx%462)/42, q=idx%42.
    //                 src row r = h + 2*(11s+j) - 20 (invalid -> zero slot).
    //   idx <  3952 : A quad. k=idx-3696, ci=k>>5, q=k&31.
    //   dst byte offset within stage = 16*idx (flat!).
    const float* srcP[TPT];
    int          strdF[TPT];
    bool         zeroT[TPT];
#pragma unroll
    for (int i = 0; i < TPT; ++i) {
        const int idx = tid + NTHR * i;
        srcP[i] = nullptr; strdF[i] = 0; zeroT[i] = false;
        if (idx < NB_TASKS) {
            const int ci  = idx / 462;
            const int rem = idx - 462 * ci;
            const int j   = rem / 42;
            const int q   = rem - 42 * j;
            const int r   = h + 2 * (s * NROW + j) - 20;
            if ((unsigned)r < (unsigned)HH) {
                srcP[i]  = g_pack2 + (((long)(b * CC_ + ci) * HH + r) * 168 + 4 * q);
                strdF[i] = CHK * HH * 168;
            } else {
                zeroT[i] = true;
            }
        } else if (idx < NTASKS) {
            const int k2 = idx - NB_TASKS;
            const int ci = k2 >> 5;
            const int q  = k2 & 31;
            srcP[i]  = g_pack1 + (((long)(b * CC_ + ci) * HH + h) * 128 + 4 * q);
            strdF[i] = CHK * HH * 128;
        }
    }

    // pre-zero invalid-row slots in ALL stages (CTA-constant, done once)
#pragma unroll
    for (int i = 0; i < TPT; ++i) {
        if (zeroT[i]) {
#pragma unroll
            for (int st = 0; st < NSTAGE; ++st) {
                *reinterpret_cast<float4*>(
                    reinterpret_cast<char*>(sm) + st * STAGE_BYTES
                    + tid * 16 + 5632 * i) = make_float4(0.f, 0.f, 0.f, 0.f);
            }
        }
    }

    // issue one chunk into a stage; advances all src pointers
    auto issue = [&](int stage) {
        const uint32_t dstBase = smbase + stage * STAGE_BYTES + tid * 16;
#pragma unroll
        for (int i = 0; i < TPT; ++i) {
            if (srcP[i]) {
                cp16(dstBase + 5632u * i, srcP[i]);
                srcP[i] += strdF[i];
            }
        }
        cp_commit();
    };

    // ---- accumulators (paired along dxi; per-kk phase keeps operands
    //      even-aligned so they come straight from LDS.128 pairs) ----
    uint64_t accp[4][10];
    float    accs[4];
#pragma unroll
    for (int kk = 0; kk < 4; ++kk) {
        accs[kk] = 0.0f;
#pragma unroll
        for (int p = 0; p < 10; ++p) accp[kk][p] = 0ull;
    }

    auto computeStage = [&](int stage) {
        const float* Bb = sm + stage * STAGE_FLOATS;
        const float* Ab = Bb + B_STAGE_FLOATS;
#pragma unroll
        for (int ci = 0; ci < CHK; ++ci) {
            const float4 q4 = *reinterpret_cast<const float4*>(
                Ab + ci * 128 + par * 64 + 4 * xi);
            uint64_t qp[4];
            qp[0] = pk2(q4.x, q4.x);
            qp[1] = pk2(q4.y, q4.y);
            qp[2] = pk2(q4.z, q4.z);
            qp[3] = pk2(q4.w, q4.w);

            const ulonglong2* Bq = reinterpret_cast<const ulonglong2*>(
                Bb + (ci * NROW + ty) * 168 + par * 84 + 4 * xi);
            uint64_t ep[12];
#pragma unroll
            for (int t = 0; t < 6; ++t) {
                const ulonglong2 v = Bq[t];
                ep[2 * t]     = v.x;
                ep[2 * t + 1] = v.y;
            }

#pragma unroll
            for (int p = 0; p < 10; ++p) {
                ffma2(accp[0][p], qp[0], ep[p]);
                ffma2(accp[1][p], qp[1], ep[p + 1]);
                ffma2(accp[2][p], qp[2], ep[p + 1]);
                ffma2(accp[3][p], qp[3], ep[p + 2]);
            }
            float lo10, hi10, lo11, hi11, lo0, hi0, lo1, hi1;
            upk2(ep[10], lo10, hi10);
            upk2(ep[11], lo11, hi11);
            upk2(ep[0],  lo0,  hi0);
            upk2(ep[1],  lo1,  hi1);
            accs[0] = fmaf(q4.x, lo10, accs[0]);
            accs[2] = fmaf(q4.z, lo11, accs[2]);
            accs[1] = fmaf(q4.y, hi0,  accs[1]);
            accs[3] = fmaf(q4.w, hi1,  accs[3]);
        }
    };

    // ---- 3-stage pipeline, one barrier per chunk, no STS to drain ----
    issue(0);                 // chunk 0 -> stage 0
    issue(1);                 // chunk 1 -> stage 1

    for (int k = 0; k < NCHK; ++k) {
        if (k < NCHK - 1) {
            asm volatile("cp.async.wait_group 1;" ::: "memory");  // chunk k done
        } else {
            asm volatile("cp.async.wait_group 0;" ::: "memory");
        }
        __syncthreads();      // all threads' chunk-k copies visible;
                              // all threads done computing chunk k-1
        if (k + 2 < NCHK) issue((k + 2) % NSTAGE);
        if (active) computeStage(k % NSTAGE);
    }

    // ---- write results ----
    if (active) {
        const float scale = 1.0f / 256.0f;
        const int obase = ((b * DD + dy_idx * GG) * HH + h) * WW + base_w;
#pragma unroll
        for (int kk = 0; kk < 4; ++kk) {
            const int dxi0 = (kk & 1) ? 1 : 0;
#pragma unroll
            for (int p = 0; p < 10; ++p) {
                float lo, hi;
                upk2(accp[kk][p], lo, hi);
                const int d0 = dxi0 + 2 * p;
                out[obase + d0 * (HH * WW) + 2 * kk]       = lo * scale;
                out[obase + (d0 + 1) * (HH * WW) + 2 * kk] = hi * scale;
            }
            const int ds = (kk & 1) ? 0 : 20;
            out[obase + ds * (HH * WW) + 2 * kk] = accs[kk] * scale;
        }
    }
}

extern "C" void kernel_launch(void* const* d_in, const int* in_sizes, int n_in,
                              void* d_out, int out_size)
{
    const float* in1 = (const float*)d_in[0];
    const float* in2 = (const float*)d_in[1];
    float* out = (float*)d_out;

    (void)in_sizes; (void)n_in; (void)out_size;

    cudaFuncSetAttribute(corr_kernel,
                         cudaFuncAttributeMaxDynamicSharedMemorySize,
                         SMEM_BYTES);

    // prepass: parity-pack inputs into scratch
    dim3 pgrid(CB * CC_ * HH, 2);
    pack_kernel<<<pgrid, 96>>>(in1, in2);

    // main
    dim3 grid(2, HH, CB);
    dim3 block(32, NROW, 1);
    corr_kernel<<<grid, block, SMEM_BYTES>>>(out);
}

// round 10
// speedup vs baseline: 1.8738x; 1.6918x over previous
#include <cuda_runtime.h>
#include <cuda_bf16.h>
#include <cstdint>

// FlowNet correlation — R9: banded parity-space Gram via mma.sync (bf16 hi/lo).
// out[b, dyi*21+dxi, h, w] = (1/256) * sum_c in1[b,c,h,w] * in2[b,c,h+dy,w+dx]
// dy = 2*(dyi-10), dx = 2*(dxi-10) -> same-parity columns only.
// Parity space: i = w>>1 (64 positions per parity); band j - i = dxi-10 in [-10,10].
// Per (b,h,dy,par): 64x64x256 Gram restricted to 4 row-blocks x 5 col-tiles (16x8).
// Precision: bf16 hi/lo split, 3 MMA terms (hi*hi + lo*hi + hi*lo), fp32 accum.
// tcgen05 is blocked (harness targets compute_100, no 'a' features); mma.sync
// m16n8k16 + ldmatrix are baseline sm_80 PTX and run on the tensor pipe.

#define CB   8
#define CC_  256
#define HH   96
#define WW   128
#define GG   21
#define DD   441

#define QBLOB  131072L     // per (b,h):  [par][hl][kc][64 rows][128B]  (16 x 8KB)
#define KTILE  11264       // per (par,hl): 88 rows x 128B  (rows 0-9,74-87 zero)
#define KCHUNK 45056       // per kc: [par][hl] x KTILE
#define KBLOB  180224L     // per (b,r): 4 kc x KCHUNK

#define QOFF   0
#define KOFF   131072
#define SDOFF  221184                  // 21*128 f32 dump
#define SMEM_REQ 232064                // <= 232448 (227KB cap)

__device__ __align__(128) char g1[(long)CB * HH * QBLOB];   // ~96 MB
__device__ __align__(128) char g2[(long)CB * HH * KBLOB];   // ~132 MB

// ---------------- helpers ----------------
__device__ __forceinline__ uint32_t smem_u32(const void* p) {
    uint32_t a;
    asm("{ .reg .u64 t; cvta.to.shared.u64 t, %1; cvt.u32.u64 %0, t; }"
        : "=r"(a) : "l"(p));
    return a;
}
__device__ __forceinline__ void cp16(uint32_t dst, const void* src) {
    asm volatile("cp.async.cg.shared.global [%0], [%1], 16;"
                 :: "r"(dst), "l"(src));
}
__device__ __forceinline__ void cp_commit() {
    asm volatile("cp.async.commit_group;" ::: "memory");
}
__device__ __forceinline__ void cp_wait1() {
    asm volatile("cp.async.wait_group 1;" ::: "memory");
}
__device__ __forceinline__ void cp_wait0() {
    asm volatile("cp.async.wait_group 0;" ::: "memory");
}
__device__ __forceinline__ void ldmA(uint32_t a[4], uint32_t addr) {
    asm volatile("ldmatrix.sync.aligned.m8n8.x4.shared.b16 {%0,%1,%2,%3}, [%4];"
        : "=r"(a[0]), "=r"(a[1]), "=r"(a[2]), "=r"(a[3]) : "r"(addr));
}
__device__ __forceinline__ void ldmB(uint32_t bq[2], uint32_t addr) {
    asm volatile("ldmatrix.sync.aligned.m8n8.x2.shared.b16 {%0,%1}, [%2];"
        : "=r"(bq[0]), "=r"(bq[1]) : "r"(addr));
}
__device__ __forceinline__ void mma16816(float c[4], const uint32_t a[4],
                                         const uint32_t bq[2]) {
    asm volatile("mma.sync.aligned.m16n8k16.row.col.f32.bf16.bf16.f32 "
        "{%0,%1,%2,%3}, {%4,%5,%6,%7}, {%8,%9}, {%0,%1,%2,%3};"
        : "+f"(c[0]), "+f"(c[1]), "+f"(c[2]), "+f"(c[3])
        : "r"(a[0]), "r"(a[1]), "r"(a[2]), "r"(a[3]), "r"(bq[0]), "r"(bq[1]));
}
__device__ __forceinline__ unsigned short cvt_hl(float v, int hl) {
    const __nv_bfloat16 h = __float2bfloat16(v);
    if (!hl) return __bfloat16_as_ushort(h);
    return __bfloat16_as_ushort(__float2bfloat16(v - __bfloat162float(h)));
}

// ---------------- prepass: fp32 -> swizzled bf16 hi/lo parity tiles ----------
__global__ void prep_kernel(const float* __restrict__ in1,
                            const float* __restrict__ in2)
{
    __shared__ float st[64][132];
    const int kc = blockIdx.x, hh = blockIdx.y;       // hh = h (Q) or r (K)
    const int b = blockIdx.z >> 1, inp = blockIdx.z & 1;
    const float* src = inp ? in2 : in1;

    for (int i = threadIdx.x; i < 64 * 32; i += 256) {
        const int c = i >> 5, q = i & 31;
        const float4 v = *reinterpret_cast<const float4*>(
            src + (((long)(b * CC_ + kc * 64 + c)) * HH + hh) * WW + 4 * q);
        st[c][4*q+0] = v.x; st[c][4*q+1] = v.y;
        st[c][4*q+2] = v.z; st[c][4*q+3] = v.w;
    }
    __syncthreads();

    if (!inp) {
        char* base = g1 + (long)(b * HH + hh) * QBLOB;
        for (int e = threadIdx.x; e < 2048; e += 256) {
            const int c8 = e & 7, s = (e >> 3) & 63;
            const int hl = (e >> 9) & 1, par = (e >> 10) & 1;
            const int w = 2 * s + par;
            uint32_t pk[4];
#pragma unroll
            for (int k = 0; k < 4; ++k) {
                const unsigned short u0 = cvt_hl(st[c8*8 + 2*k][w], hl);
                const unsigned short u1 = cvt_hl(st[c8*8 + 2*k + 1][w], hl);
                pk[k] = (uint32_t)u0 | ((uint32_t)u1 << 16);
            }
            char* tile = base + (long)(((par*2 + hl)*4 + kc)) * 8192;
            *reinterpret_cast<uint4*>(tile + s*128 + ((c8 ^ (s & 7)) << 4)) =
                make_uint4(pk[0], pk[1], pk[2], pk[3]);
        }
    } else {
        char* base = g2 + (long)(b * HH + hh) * KBLOB;
        for (int e = threadIdx.x; e < 2816; e += 256) {
            const int c8 = e & 7;
            const int jp = (e >> 3) % 88;
            const int hlp = e / (8 * 88);
            const int hl = hlp & 1, par = hlp >> 1;
            uint4 val = make_uint4(0u, 0u, 0u, 0u);
            if (jp >= 10 && jp < 74) {
                const int w = 2 * (jp - 10) + par;
                uint32_t pk[4];
#pragma unroll
                for (int k = 0; k < 4; ++k) {
                    const unsigned short u0 = cvt_hl(st[c8*8 + 2*k][w], hl);
                    const unsigned short u1 = cvt_hl(st[c8*8 + 2*k + 1][w], hl);
                    pk[k] = (uint32_t)u0 | ((uint32_t)u1 << 16);
                }
                val = make_uint4(pk[0], pk[1], pk[2], pk[3]);
            }
            char* tile = base + (long)(kc*4 + par*2 + hl) * KTILE;
            *reinterpret_cast<uint4*>(tile + jp*128 + ((c8 ^ (jp & 7)) << 4)) = val;
        }
    }
}

// ---------------- main kernel ----------------
__global__ __launch_bounds__(256, 1)
void corr_mma_kernel(float* __restrict__ out)
{
    extern __shared__ char smraw[];
    const uint32_t rawS = smem_u32(smraw);
    const uint32_t smb = (rawS + 127) & ~127u;
    char* smA = smraw + (smb - rawS);

    const int tid = threadIdx.x, lane = tid & 31, wid = tid >> 5;
    const int h = blockIdx.x, b = blockIdx.y;
    const int p = wid & 1, i0 = (wid >> 1) * 16;

    const int dyimin = (h >= 20) ? 0 : ((21 - h) >> 1);
    const int dyimax = min(20, (115 - h) >> 1);
    const int nv = dyimax - dyimin + 1;
    const int NC = 4 * nv;

    const long obase_bh = (long)b * DD * HH * WW + (long)h * WW;

    // zero planes for invalid dy
    for (int dyi = 0; dyi < GG; ++dyi) {
        if (dyi >= dyimin && dyi <= dyimax) continue;
        const long pb = obase_bh + (long)(dyi * GG) * (HH * WW);
        for (int e = tid; e < GG * WW; e += 256) {
            out[pb + (long)(e >> 7) * (HH * WW) + (e & 127)] = 0.0f;
        }
    }

    // K chunk issue (one commit group per chunk)
    auto issueK = [&](int c, int stage) {
        const int vidx = c >> 2, kc = c & 3;
        const int r = h + 2 * (dyimin + vidx) - 20;
        const char* src = g2 + (long)(b * HH + r) * KBLOB + (long)kc * KCHUNK;
        const uint32_t dst = smb + KOFF + (uint32_t)stage * KCHUNK;
#pragma unroll
        for (int o = 0; o < 11; ++o) {
            const int t = tid + 256 * o;
            cp16(dst + (uint32_t)t * 16, src + (long)t * 16);
        }
        cp_commit();
    };

    // prologue: Q (+K0) as group 0, K1 as group 1
    {
        const char* qsrc = g1 + (long)(b * HH + h) * QBLOB;
#pragma unroll
        for (int o = 0; o < 32; ++o) {
            const int t = tid + 256 * o;
            cp16(smb + QOFF + (uint32_t)t * 16, qsrc + (long)t * 16);
        }
        // K chunk 0 folded into the same group as Q
        const int r0v = h + 2 * dyimin - 20;
        const char* ks = g2 + (long)(b * HH + r0v) * KBLOB;
        const uint32_t dst = smb + KOFF;
#pragma unroll
        for (int o = 0; o < 11; ++o) {
            const int t = tid + 256 * o;
            cp16(dst + (uint32_t)t * 16, ks + (long)t * 16);
        }
        cp_commit();
        issueK(1, 1);
    }

    // per-lane ldmatrix address constants
    const int matA = lane >> 3;
    const int rA   = (lane & 7) + ((matA & 1) << 3);
    const int ckA  = matA >> 1;
    const uint32_t aRow = (uint32_t)(i0 + rA) * 128;
    const int swA = lane & 7;
    const int rB = lane & 7;
    const int matB = (lane >> 3) & 1;
    const uint32_t bRow = (uint32_t)(i0 + rB) * 128;

    float C[5][4];
#pragma unroll
    for (int t = 0; t < 5; ++t)
#pragma unroll
        for (int g = 0; g < 4; ++g) C[t][g] = 0.0f;

    const float scale = 1.0f / 256.0f;
    float* sd = reinterpret_cast<float*>(smA + SDOFF);
    const int r0l = lane >> 2, n0l = (lane & 3) * 2;

    for (int c = 0; c < NC; ++c) {
        if (c + 1 < NC) cp_wait1(); else cp_wait0();
        __syncthreads();                       // stage (c&1) visible CTA-wide

        // ---- compute chunk c ----
        {
            const int kc = c & 3;
            const uint32_t qhi = smb + QOFF + (uint32_t)((p*2 + 0)*4 + kc) * 8192;
            const uint32_t qlo = smb + QOFF + (uint32_t)((p*2 + 1)*4 + kc) * 8192;
            const uint32_t khi = smb + KOFF + (uint32_t)(c & 1) * KCHUNK
                               + (uint32_t)(p * 2) * KTILE;
            const uint32_t klo = khi + KTILE;
#pragma unroll
            for (int k = 0; k < 4; ++k) {
                uint32_t aH[4], aL[4], bH[2], bL[2];
                const uint32_t ao = aRow + ((uint32_t)((2*k + ckA) ^ swA) << 4);
                ldmA(aH, qhi + ao);
                ldmA(aL, qlo + ao);
                const uint32_t bo = bRow + ((uint32_t)((2*k + matB) ^ rB) << 4);
#pragma unroll
                for (int t = 0; t < 5; ++t) {
                    ldmB(bH, khi + bo + (uint32_t)t * 1024);
                    mma16816(C[t], aH, bH);
                    mma16816(C[t], aL, bH);
                    ldmB(bL, klo + bo + (uint32_t)t * 1024);
                    mma16816(C[t], aH, bL);
                }
            }
        }

        // ---- epilogue after last kc of a dy ----
        if ((c & 3) == 3) {
            const int dyi = dyimin + (c >> 2);
#pragma unroll
            for (int t = 0; t < 5; ++t)
#pragma unroll
                for (int g = 0; g < 4; ++g) {
                    const int row = r0l + ((g & 2) ? 8 : 0);
                    const int col = n0l + (g & 1);
                    const int dxi = 8 * t + col - row;
                    if (dxi >= 0 && dxi < GG)
                        sd[dxi * WW + 2 * (i0 + row) + p] = C[t][g] * scale;
                    C[t][g] = 0.0f;
                }
            __syncthreads();                    // sd complete
            const long pb = obase_bh + (long)(dyi * GG) * (HH * WW);
            for (int e = tid; e < GG * WW; e += 256) {
                out[pb + (long)(e >> 7) * (HH * WW) + (e & 127)] = sd[e];
            }
        }

        __syncthreads();                        // stage (c&1) drained; sd read
        if (c + 2 < NC) issueK(c + 2, c & 1);
    }
}

extern "C" void kernel_launch(void* const* d_in, const int* in_sizes, int n_in,
                              void* d_out, int out_size)
{
    const float* in1 = (const float*)d_in[0];
    const float* in2 = (const float*)d_in[1];
    float* out = (float*)d_out;
    (void)in_sizes; (void)n_in; (void)out_size;

    cudaFuncSetAttribute(corr_mma_kernel,
                         cudaFuncAttributeMaxDynamicSharedMemorySize, SMEM_REQ);

    dim3 pgrid(4, HH, CB * 2);
    prep_kernel<<<pgrid, 256>>>(in1, in2);

    dim3 grid(HH, CB);
    corr_mma_kernel<<<grid, 256, SMEM_REQ>>>(out);
}